// round 16
// baseline (speedup 1.0000x reference)
#include <cuda_runtime.h>
#include <cuda_bf16.h>
#include <math.h>
#include <stdint.h>

#define NB     1024
#define NCP    20000
#define NF     10001
#define NPAIR  512
#define KP     10240      // padded K for tensor GEMM
#define TSPLIT 4          // split-K for tensor layer-0 GEMM
#define NSPLIT 4          // split-K for SIMT layers 1,2

// ---------------- device scratch (no allocations allowed) ----------------
__device__ __nv_bfloat16 g_Ahi[(size_t)NB * KP];
__device__ __nv_bfloat16 g_Alo[(size_t)NB * KP];
__device__ __nv_bfloat16 g_A2h[(size_t)NB * KP];
__device__ __nv_bfloat16 g_Whi[(size_t)256 * KP];
__device__ __nv_bfloat16 g_Wlo[(size_t)256 * KP];
__device__ __nv_bfloat16 g_Shi[(size_t)256 * KP];
__device__ float  g_S1[128 * 256];
__device__ float  g_S2[64 * 128];
__device__ float  g_invn0[NB];
__device__ float  g_invn1[NB];
__device__ float  g_invn2[NB];
__device__ float  g_invn3[NB];
__device__ float  g_Yp[TSPLIT * NB * 256];
__device__ float  g_Pp[TSPLIT * NB * 256];
__device__ float  g_act1[NB * 256];
__device__ float  g_act2[NB * 128];
__device__ float  g_act3[NB * 64];

// ---------------- helpers ----------------
__device__ __forceinline__ float2 cmul(float2 a, float2 b) {
    return make_float2(a.x * b.x - a.y * b.y, a.x * b.y + a.y * b.x);
}
__device__ __forceinline__ float2 cadd(float2 a, float2 b) {
    return make_float2(a.x + b.x, a.y + b.y);
}
__device__ __forceinline__ float2 csub(float2 a, float2 b) {
    return make_float2(a.x - b.x, a.y - b.y);
}
__device__ __forceinline__ float blockReduce(float v, float* sb, int tid, int n) {
    sb[tid] = v; __syncthreads();
    for (int s = n >> 1; s > 0; s >>= 1) {
        if (tid < s) sb[tid] += sb[tid + s];
        __syncthreads();
    }
    float r = sb[0]; __syncthreads();
    return r;
}
__device__ __forceinline__ int posidx(int k) {
    int d0 = k % 10; k /= 10;
    int d1 = k % 10; k /= 10;
    int d2 = k % 10; k /= 10;
    int d3 = k % 10; int d4 = k / 10;
    return d0 * 2000 + d1 * 200 + d2 * 20 + d3 * 2 + d4;
}
__device__ __forceinline__ uint32_t smem_u32(const void* p) {
    uint32_t a;
    asm("{ .reg .u64 t; cvta.to.shared.u64 t, %1; cvt.u32.u64 %0, t; }" : "=r"(a) : "l"(p));
    return a;
}
#define CP16(dst, src) \
    asm volatile("cp.async.cg.shared.global [%0], [%1], 16;" :: "r"(dst), "l"(src))
#define CP_COMMIT() asm volatile("cp.async.commit_group;")

// mma.sync m16n8k16 bf16 (sm_80+ PTX; works on plain sm_103 target)
__device__ __forceinline__ void mma16816(float* d, const uint32_t* a, const uint32_t* b) {
    asm volatile(
        "mma.sync.aligned.m16n8k16.row.col.f32.bf16.bf16.f32 "
        "{%0,%1,%2,%3}, {%4,%5,%6,%7}, {%8,%9}, {%0,%1,%2,%3};"
        : "+f"(d[0]), "+f"(d[1]), "+f"(d[2]), "+f"(d[3])
        : "r"(a[0]), "r"(a[1]), "r"(a[2]), "r"(a[3]), "r"(b[0]), "r"(b[1]));
}

// ---------------- init kernels ----------------
__global__ void sigmoid_k(const float* __restrict__ a, float* __restrict__ s, int n) {
    for (int i = blockIdx.x * blockDim.x + threadIdx.x; i < n; i += gridDim.x * blockDim.x)
        s[i] = 1.0f / (1.0f + expf(-a[i]));
}
// W-side conversion: Whi/Wlo split + Shi = bf16(sigmoid(alpha)), zero-padded to KP
// grid (KP/2048 = 5, 256), block 256; 8 elements per thread, vector stores.
__global__ void convW_k(const float* __restrict__ W, const float* __restrict__ al) {
    int n = blockIdx.y;
    int k0 = (blockIdx.x * 256 + threadIdx.x) * 8;
    const float* wr = W  + (size_t)n * NF;
    const float* ar = al + (size_t)n * NF;
    __nv_bfloat16 hi8[8], lo8[8], s8[8];
    #pragma unroll
    for (int i = 0; i < 8; i++) {
        int k = k0 + i;
        float w = 0.f, s = 0.f;
        if (k < NF) {
            w = wr[k];
            s = 1.0f / (1.0f + __expf(-ar[k]));
        }
        __nv_bfloat16 h = __float2bfloat16(w);
        hi8[i] = h;
        lo8[i] = __float2bfloat16(w - __bfloat162float(h));
        s8[i]  = __float2bfloat16(s);
    }
    size_t off = (size_t)n * KP + k0;
    *reinterpret_cast<uint4*>(g_Whi + off) = *reinterpret_cast<uint4*>(hi8);
    *reinterpret_cast<uint4*>(g_Wlo + off) = *reinterpret_cast<uint4*>(lo8);
    *reinterpret_cast<uint4*>(g_Shi + off) = *reinterpret_cast<uint4*>(s8);
}

// ---------------- optimized 5-point DFT (omega5 = e^{-2pi i/5}) ----------------
__device__ __forceinline__ void dft5(float2 y0, float2 y1, float2 y2, float2 y3, float2 y4,
                                     float2& X0, float2& X1, float2& X2, float2& X3, float2& X4)
{
    const float C1 = 0.30901699437494745f, C2 = -0.8090169943749475f;
    const float S1 = 0.9510565162951535f,  S2 = 0.5877852522924731f;
    float2 t1 = cadd(y1, y4), t2 = cadd(y2, y3);
    float2 d1 = csub(y1, y4), d2 = csub(y2, y3);
    X0 = make_float2(y0.x + t1.x + t2.x, y0.y + t1.y + t2.y);
    float2 a1 = make_float2(fmaf(C1, t1.x, fmaf(C2, t2.x, y0.x)),
                            fmaf(C1, t1.y, fmaf(C2, t2.y, y0.y)));
    float2 a2 = make_float2(fmaf(C2, t1.x, fmaf(C1, t2.x, y0.x)),
                            fmaf(C2, t1.y, fmaf(C1, t2.y, y0.y)));
    float2 b1 = make_float2(fmaf(S1, d1.x,  S2 * d2.x), fmaf(S1, d1.y,  S2 * d2.y));
    float2 b2 = make_float2(fmaf(S2, d1.x, -S1 * d2.x), fmaf(S2, d1.y, -S1 * d2.y));
    X1 = make_float2(a1.x + b1.y, a1.y - b1.x);
    X4 = make_float2(a1.x - b1.y, a1.y + b1.x);
    X2 = make_float2(a2.x + b2.y, a2.y - b2.x);
    X3 = make_float2(a2.x - b2.y, a2.y + b2.x);
}

// ------------- radix-10 in-place DIF stage via 2x5 split; MUFU twiddles -------------
template<int NN, int MM>
__device__ __forceinline__ void r10_stage(float2* Z, int t)
{
    const float2 W1_ = make_float2( 0.8090169943749475f,  -0.5877852522924731f);
    const float2 W2_ = make_float2( 0.30901699437494745f, -0.9510565162951535f);
    const float2 W3_ = make_float2(-0.30901699437494745f, -0.9510565162951535f);
    const float2 W4_ = make_float2(-0.8090169943749475f,  -0.5877852522924731f);
    constexpr float NEG2PI = -6.28318530717958647692f / (float)NN;
    for (int g = t; g < 2000; g += 1024) {
        int blk = g / MM, j = g - blk * MM;
        int base = blk * NN + j;
        float2 c[10];
        #pragma unroll
        for (int u = 0; u < 10; u++) c[u] = Z[base + u * MM];
        float2 e0 = cadd(c[0], c[5]), e1 = cadd(c[1], c[6]), e2 = cadd(c[2], c[7]),
               e3 = cadd(c[3], c[8]), e4 = cadd(c[4], c[9]);
        float2 o0 = csub(c[0], c[5]);
        float2 o1 = cmul(csub(c[1], c[6]), W1_);
        float2 o2 = cmul(csub(c[2], c[7]), W2_);
        float2 o3 = cmul(csub(c[3], c[8]), W3_);
        float2 o4 = cmul(csub(c[4], c[9]), W4_);
        float2 X[10];
        dft5(e0, e1, e2, e3, e4, X[0], X[2], X[4], X[6], X[8]);
        dft5(o0, o1, o2, o3, o4, X[1], X[3], X[5], X[7], X[9]);
        Z[base] = X[0];
        float ang = NEG2PI * (float)j;
        #pragma unroll
        for (int v = 1; v < 10; v++) {
            float s, co;
            __sincosf(ang * (float)v, &s, &co);
            Z[base + v * MM] = cmul(X[v], make_float2(co, s));
        }
    }
}

// ---- fused FFT (packed 2 rows) + unpack + log1p|.| + norms + bf16 split out ----
__global__ void __launch_bounds__(1024, 1) fft_k(const float* __restrict__ x)
{
    extern __shared__ float2 Z[];   // 20000 complex, in-place FFT
    __shared__ float sred[64];
    int p = blockIdx.x, t = threadIdx.x;
    const float* xa = x + (size_t)(2 * p) * NCP;
    const float* xb = xa + NCP;
    for (int i = t; i < NCP; i += 1024) Z[i] = make_float2(xa[i], xb[i]);
    __syncthreads();

    r10_stage<20000, 2000>(Z, t); __syncthreads();
    r10_stage< 2000,  200>(Z, t); __syncthreads();
    r10_stage<  200,   20>(Z, t); __syncthreads();
    r10_stage<   20,    2>(Z, t); __syncthreads();
    for (int g = t; g < 10000; g += 1024) {
        float2 c0 = Z[2 * g], c1 = Z[2 * g + 1];
        Z[2 * g]     = make_float2(c0.x + c1.x, c0.y + c1.y);
        Z[2 * g + 1] = make_float2(c0.x - c1.x, c0.y - c1.y);
    }
    __syncthreads();

    size_t rowA = (size_t)(2 * p) * KP, rowB = rowA + KP;
    float na = 0.f, nb = 0.f;
    for (int k = t; k < NF; k += 1024) {
        float va, vb;
        if (k == 0) { va = 0.f; vb = 0.f; }
        else {
            float2 zk = Z[posidx(k)];
            float2 zr = Z[posidx(20000 - k)];
            float are = 0.5f * (zk.x + zr.x), aim = 0.5f * (zk.y - zr.y);
            float bre = 0.5f * (zk.y + zr.y), bim = 0.5f * (zr.x - zk.x);
            va = log1pf(sqrtf(fmaf(are, are, aim * aim)));
            vb = log1pf(sqrtf(fmaf(bre, bre, bim * bim)));
        }
        __nv_bfloat16 ha = __float2bfloat16(va), hb = __float2bfloat16(vb);
        g_Ahi[rowA + k] = ha;
        g_Ahi[rowB + k] = hb;
        g_Alo[rowA + k] = __float2bfloat16(va - __bfloat162float(ha));
        g_Alo[rowB + k] = __float2bfloat16(vb - __bfloat162float(hb));
        g_A2h[rowA + k] = __float2bfloat16(va * va);
        g_A2h[rowB + k] = __float2bfloat16(vb * vb);
        na = fmaf(va, va, na); nb = fmaf(vb, vb, nb);
    }
    for (int k = NF + t; k < KP; k += 1024) {
        __nv_bfloat16 z0 = __float2bfloat16(0.f);
        g_Ahi[rowA + k] = z0; g_Ahi[rowB + k] = z0;
        g_Alo[rowA + k] = z0; g_Alo[rowB + k] = z0;
        g_A2h[rowA + k] = z0; g_A2h[rowB + k] = z0;
    }
    #pragma unroll
    for (int off = 16; off > 0; off >>= 1) {
        na += __shfl_down_sync(0xffffffffu, na, off);
        nb += __shfl_down_sync(0xffffffffu, nb, off);
    }
    int wid = t >> 5, lane = t & 31;
    if (lane == 0) { sred[wid] = na; sred[32 + wid] = nb; }
    __syncthreads();
    if (t == 0) {
        float s1 = 0.f, s2 = 0.f;
        for (int i = 0; i < 32; i++) { s1 += sred[i]; s2 += sred[32 + i]; }
        g_invn0[2 * p]     = 1.0f / (sqrtf(s1) + 1e-8f);
        g_invn0[2 * p + 1] = 1.0f / (sqrtf(s2) + 1e-8f);
    }
}

// ------------- layer-0 dual GEMM via mma.sync bf16, cp.async double-buffered -----
// BM=128, BN=64, BK=32, 256 threads (8 warps, 4x2), warp tile 32x32.
// grid: (256/64=4, 1024/128=8, TSPLIT=4) = 128 CTAs = one wave.
#define SST 40                          // smem row stride in bf16
#define ABYTES (128 * SST * 2)          // 10240 B per A tile
#define WBYTES (64 * SST * 2)           // 5120 B per W tile
#define WOFF   (3 * ABYTES)             // 30720
#define BUFSZ  (3 * ABYTES + 3 * WBYTES) // 46080
__global__ void __launch_bounds__(256, 1) tgemm0_k(float* __restrict__ Yp, float* __restrict__ Pp)
{
    extern __shared__ __align__(16) char smg[];
    int t = threadIdx.x, wid = t >> 5, lane = t & 31;
    int wm = wid & 3, wn = wid >> 2;
    int n0 = blockIdx.x * 64, m0 = blockIdx.y * 128, z = blockIdx.z;
    int kbase = z * (KP / TSPLIT);
    const int NKB = (KP / TSPLIT) / 32;   // 80
    uint32_t sbase = smem_u32(smg);

    const __nv_bfloat16* Asrc[3] = { g_Ahi, g_Alo, g_A2h };
    const __nv_bfloat16* Bsrc[3] = { g_Whi, g_Wlo, g_Shi };

    auto load_blk = [&](int buf, int k0) {
        uint32_t db = sbase + (uint32_t)buf * BUFSZ;
        #pragma unroll
        for (int e = t; e < 1536; e += 256) {
            int tile = e >> 9, v = e & 511;
            int r = v >> 2, c4 = v & 3;
            const void* src = Asrc[tile] + ((size_t)(m0 + r) * KP + k0 + c4 * 8);
            CP16(db + tile * ABYTES + (uint32_t)(r * SST + c4 * 8) * 2, src);
        }
        #pragma unroll
        for (int e = t; e < 768; e += 256) {
            int tile = e >> 8, v = e & 255;
            int r = v >> 2, c4 = v & 3;
            const void* src = Bsrc[tile] + ((size_t)(n0 + r) * KP + k0 + c4 * 8);
            CP16(db + WOFF + tile * WBYTES + (uint32_t)(r * SST + c4 * 8) * 2, src);
        }
        CP_COMMIT();
    };

    float yacc[2][4][4] = {}, pacc[2][4][4] = {};
    int q = lane & 3, gp = lane >> 2;

    load_blk(0, kbase);
    for (int kb = 0; kb < NKB; kb++) {
        if (kb + 1 < NKB) {
            load_blk((kb + 1) & 1, kbase + (kb + 1) * 32);
            asm volatile("cp.async.wait_group 1;");
        } else {
            asm volatile("cp.async.wait_group 0;");
        }
        __syncthreads();
        const __nv_bfloat16* sb = reinterpret_cast<const __nv_bfloat16*>(smg + (kb & 1) * BUFSZ);
        #pragma unroll
        for (int ks = 0; ks < 32; ks += 16) {
            uint32_t fa[3][2][4];
            #pragma unroll
            for (int pr = 0; pr < 3; pr++) {
                const __nv_bfloat16* sa = sb + pr * (128 * SST);
                #pragma unroll
                for (int mt = 0; mt < 2; mt++) {
                    int row = wm * 32 + mt * 16 + gp;
                    int kk = ks + q * 2;
                    fa[pr][mt][0] = *reinterpret_cast<const uint32_t*>(sa + row * SST + kk);
                    fa[pr][mt][1] = *reinterpret_cast<const uint32_t*>(sa + (row + 8) * SST + kk);
                    fa[pr][mt][2] = *reinterpret_cast<const uint32_t*>(sa + row * SST + kk + 8);
                    fa[pr][mt][3] = *reinterpret_cast<const uint32_t*>(sa + (row + 8) * SST + kk + 8);
                }
            }
            uint32_t fb[3][4][2];
            #pragma unroll
            for (int pr = 0; pr < 3; pr++) {
                const __nv_bfloat16* sw = sb + 3 * (128 * SST) + pr * (64 * SST);
                #pragma unroll
                for (int nt = 0; nt < 4; nt++) {
                    int nrow = wn * 32 + nt * 8 + gp;
                    int kk = ks + q * 2;
                    fb[pr][nt][0] = *reinterpret_cast<const uint32_t*>(sw + nrow * SST + kk);
                    fb[pr][nt][1] = *reinterpret_cast<const uint32_t*>(sw + nrow * SST + kk + 8);
                }
            }
            #pragma unroll
            for (int mt = 0; mt < 2; mt++)
                #pragma unroll
                for (int nt = 0; nt < 4; nt++) {
                    mma16816(yacc[mt][nt], fa[0][mt], fb[0][nt]);  // Ahi*Whi
                    mma16816(yacc[mt][nt], fa[0][mt], fb[1][nt]);  // Ahi*Wlo
                    mma16816(yacc[mt][nt], fa[1][mt], fb[0][nt]);  // Alo*Whi
                    mma16816(pacc[mt][nt], fa[2][mt], fb[2][nt]);  // A2*S
                }
        }
        __syncthreads();
    }

    float* Yo = Yp + (size_t)z * NB * 256;
    float* Po = Pp + (size_t)z * NB * 256;
    #pragma unroll
    for (int mt = 0; mt < 2; mt++)
        #pragma unroll
        for (int nt = 0; nt < 4; nt++) {
            int row = m0 + wm * 32 + mt * 16 + gp;
            int col = n0 + wn * 32 + nt * 8 + q * 2;
            *reinterpret_cast<float2*>(Yo + (size_t)row * 256 + col) =
                make_float2(yacc[mt][nt][0], yacc[mt][nt][1]);
            *reinterpret_cast<float2*>(Yo + (size_t)(row + 8) * 256 + col) =
                make_float2(yacc[mt][nt][2], yacc[mt][nt][3]);
            *reinterpret_cast<float2*>(Po + (size_t)row * 256 + col) =
                make_float2(pacc[mt][nt][0], pacc[mt][nt][1]);
            *reinterpret_cast<float2*>(Po + (size_t)(row + 8) * 256 + col) =
                make_float2(pacc[mt][nt][2], pacc[mt][nt][3]);
        }
}

// ------------- SIMT dual GEMM (layers 1,2) -------------
__global__ void __launch_bounds__(256) gemm_dual_k(
    const float* __restrict__ A, const float* __restrict__ W, const float* __restrict__ S,
    float* __restrict__ Yp, float* __restrict__ Pp, int M, int N, int K, int Kc)
{
    __shared__ float sA[16][68], sW[16][68], sS[16][68];
    int t = threadIdx.x;
    int tx = t & 15, ty = t >> 4;
    int m0 = blockIdx.y * 64, n0 = blockIdx.x * 64;
    int z = blockIdx.z;
    int kbeg = z * Kc, kend = min(K, kbeg + Kc);
    float y[4][4] = {}, pq[4][4] = {};

    for (int k0 = kbeg; k0 < kend; k0 += 16) {
        #pragma unroll
        for (int i = 0; i < 4; i++) {
            int e = t + i * 256;
            int row = e >> 4, kk = e & 15;
            int gk = k0 + kk;
            bool ok = gk < kend;
            sA[kk][row] = ok ? A[(size_t)(m0 + row) * K + gk] : 0.f;
            sW[kk][row] = ok ? W[(size_t)(n0 + row) * K + gk] : 0.f;
            sS[kk][row] = ok ? S[(size_t)(n0 + row) * K + gk] : 0.f;
        }
        __syncthreads();
        #pragma unroll
        for (int kk = 0; kk < 16; kk++) {
            float av[4], wv[4], sv[4];
            #pragma unroll
            for (int i = 0; i < 4; i++) {
                av[i] = sA[kk][ty * 4 + i];
                wv[i] = sW[kk][tx * 4 + i];
                sv[i] = sS[kk][tx * 4 + i];
            }
            #pragma unroll
            for (int i = 0; i < 4; i++) {
                float a2 = av[i] * av[i];
                #pragma unroll
                for (int j = 0; j < 4; j++) {
                    y[i][j]  = fmaf(av[i], wv[j], y[i][j]);
                    pq[i][j] = fmaf(a2,    sv[j], pq[i][j]);
                }
            }
        }
        __syncthreads();
    }
    float* Yo = Yp + (size_t)z * M * N;
    float* Po = Pp + (size_t)z * M * N;
    #pragma unroll
    for (int i = 0; i < 4; i++)
        #pragma unroll
        for (int j = 0; j < 4; j++) {
            size_t off = (size_t)(m0 + ty * 4 + i) * N + (n0 + tx * 4 + j);
            Yo[off] = y[i][j]; Po[off] = pq[i][j];
        }
}

// ------------- epilogue -------------
__global__ void epi_k(const float* __restrict__ Yp, const float* __restrict__ Pp,
                      const float* __restrict__ b, const float* __restrict__ eta,
                      const float* __restrict__ g, const float* __restrict__ be,
                      const float* __restrict__ invn_in,
                      float* __restrict__ act, float* __restrict__ invn_out,
                      int H, int nsplit)
{
    __shared__ float sb[256];
    int r = blockIdx.x, o = threadIdx.x;
    size_t MN = (size_t)NB * H;
    size_t off = (size_t)r * H + o;
    float ys = b[o], pv = 0.f;
    for (int s = 0; s < nsplit; s++) { ys += Yp[s * MN + off]; pv += Pp[s * MN + off]; }
    float y = fmaf(eta[0] * tanhf(ys), invn_in[r] * pv, ys);
    float invH = 1.0f / (float)H;
    float s1 = blockReduce(y, sb, o, H);
    float s2 = blockReduce(y * y, sb, o, H);
    float mu = s1 * invH;
    float var = fmaf(s2, invH, -mu * mu);
    float ln = (y - mu) * rsqrtf(var + 1e-5f) * g[o] + be[o];
    float a = 0.5f * ln * (1.0f + erff(ln * 0.70710678118654752f));
    act[off] = a;
    float s3 = blockReduce(a * a, sb, o, H);
    if (o == 0) invn_out[r] = 1.0f / (sqrtf(s3) + 1e-8f);
}

// ------------- head -------------
__global__ void head_k(const float* __restrict__ act, const float* __restrict__ hw,
                       const float* __restrict__ hb, float* __restrict__ out)
{
    int t = threadIdx.x;
    int warp = t >> 5, lane = t & 31;
    int r = blockIdx.x * 32 + warp;
    const float* a = act + (size_t)r * 64;
    float v = fmaf(a[lane], hw[lane], a[lane + 32] * hw[lane + 32]);
    #pragma unroll
    for (int off = 16; off > 0; off >>= 1) v += __shfl_down_sync(0xffffffffu, v, off);
    if (lane == 0) out[r] = v + hb[0];
}

// ---------------- host launch ----------------
extern "C" void kernel_launch(void* const* d_in, const int* in_sizes, int n_in,
                              void* d_out, int out_size)
{
    (void)in_sizes; (void)n_in; (void)out_size;
    const float* x    = (const float*)d_in[0];
    const float* W0   = (const float*)d_in[1];
    const float* al0  = (const float*)d_in[2];
    const float* b0   = (const float*)d_in[3];
    const float* eta0 = (const float*)d_in[4];
    const float* g0   = (const float*)d_in[5];
    const float* be0  = (const float*)d_in[6];
    const float* W1   = (const float*)d_in[7];
    const float* al1  = (const float*)d_in[8];
    const float* b1   = (const float*)d_in[9];
    const float* eta1 = (const float*)d_in[10];
    const float* g1   = (const float*)d_in[11];
    const float* be1  = (const float*)d_in[12];
    const float* W2   = (const float*)d_in[13];
    const float* al2  = (const float*)d_in[14];
    const float* b2   = (const float*)d_in[15];
    const float* eta2 = (const float*)d_in[16];
    const float* g2   = (const float*)d_in[17];
    const float* be2  = (const float*)d_in[18];
    const float* hw   = (const float*)d_in[19];
    const float* hb   = (const float*)d_in[20];
    float* out = (float*)d_out;

    float *pS1, *pS2, *pYp, *pPp, *pa1, *pa2, *pa3, *pi0, *pi1, *pi2, *pi3;
    cudaGetSymbolAddress((void**)&pS1, g_S1);
    cudaGetSymbolAddress((void**)&pS2, g_S2);
    cudaGetSymbolAddress((void**)&pYp, g_Yp);
    cudaGetSymbolAddress((void**)&pPp, g_Pp);
    cudaGetSymbolAddress((void**)&pa1, g_act1);
    cudaGetSymbolAddress((void**)&pa2, g_act2);
    cudaGetSymbolAddress((void**)&pa3, g_act3);
    cudaGetSymbolAddress((void**)&pi0, g_invn0);
    cudaGetSymbolAddress((void**)&pi1, g_invn1);
    cudaGetSymbolAddress((void**)&pi2, g_invn2);
    cudaGetSymbolAddress((void**)&pi3, g_invn3);

    const int SMEM_FFT = 20000 * (int)sizeof(float2);   // 160000 B
    cudaFuncSetAttribute(fft_k, cudaFuncAttributeMaxDynamicSharedMemorySize, SMEM_FFT);
    const int SMEM_TG = 2 * BUFSZ;                      // 92160 B
    cudaFuncSetAttribute(tgemm0_k, cudaFuncAttributeMaxDynamicSharedMemorySize, SMEM_TG);

    sigmoid_k<<<64, 256>>>(al1, pS1, 128 * 256);
    sigmoid_k<<<16, 256>>>(al2, pS2, 64 * 128);
    convW_k<<<dim3(KP / 2048, 256), 256>>>(W0, al0);

    fft_k<<<NPAIR, 1024, SMEM_FFT>>>(x);

    tgemm0_k<<<dim3(4, 8, TSPLIT), 256, SMEM_TG>>>(pYp, pPp);
    epi_k<<<NB, 256>>>(pYp, pPp, b0, eta0, g0, be0, pi0, pa1, pi1, 256, TSPLIT);

    int Kc1 = ((256 + NSPLIT * 16 - 1) / (NSPLIT * 16)) * 16;  // 64
    int Kc2 = ((128 + NSPLIT * 16 - 1) / (NSPLIT * 16)) * 16;  // 32
    gemm_dual_k<<<dim3(128 / 64, NB / 64, NSPLIT), 256>>>(pa1, W1, pS1, pYp, pPp, NB, 128, 256, Kc1);
    epi_k<<<NB, 128>>>(pYp, pPp, b1, eta1, g1, be1, pi1, pa2, pi2, 128, NSPLIT);
    gemm_dual_k<<<dim3(64 / 64,  NB / 64, NSPLIT), 256>>>(pa2, W2, pS2, pYp, pPp, NB, 64, 128, Kc2);
    epi_k<<<NB, 64>>>(pYp, pPp, b2, eta2, g2, be2, pi2, pa3, pi3, 64, NSPLIT);
    head_k<<<NB / 32, 1024>>>(pa3, hw, hb, out);
}